// round 12
// baseline (speedup 1.0000x reference)
#include <cuda_runtime.h>
#include <cuda_bf16.h>

// One wave: 148 SMs x 6 CTAs. Block-contiguous partition for DRAM row locality.
#define NBLOCKS 888
#define NTHREADS 256
#define NWARPS (NTHREADS / 32)

__device__ float g_partials[NBLOCKS];
__device__ unsigned int g_count = 0;

// class(x) = clamp(floor(x), -1, 2) + 1  in {0,1,2,3}
__device__ __forceinline__ int cls_of(float x) {
    int i = __float2int_rd(x);   // CVT.RMI
    i = max(i, -1);
    i = min(i, 2);
    return i + 1;
}

__device__ __forceinline__ float quad_term(const float* __restrict__ w,
                                           float4 p, float4 t) {
    float d0 = p.x - t.x;
    float d1 = p.y - t.y;
    float d2 = p.z - t.z;
    float d3 = p.w - t.w;

    float w0 = w[cls_of(t.x) * 4 + cls_of(p.x)];
    float w1 = w[cls_of(t.y) * 4 + cls_of(p.y)];
    float w2 = w[cls_of(t.z) * 4 + cls_of(p.z)];
    float w3 = w[cls_of(t.w) * 4 + cls_of(p.w)];

    float s01 = fmaf(d0 * d0, w0, d1 * d1 * w1);
    float s23 = fmaf(d2 * d2, w2, d3 * d3 * w3);
    return s01 + s23;
}

__global__ void __launch_bounds__(NTHREADS, 6)
gmgs_fused_kernel(const float4* __restrict__ pred,
                  const float4* __restrict__ tru,
                  const float* __restrict__ score,
                  int n4, float inv_B, float* __restrict__ out)
{
    __shared__ float w[16];
    __shared__ float swarp[NWARPS];
    __shared__ bool s_is_last;

    if (threadIdx.x == 0) {
        float e[16];
        float tot = 0.0f;
        #pragma unroll
        for (int i = 0; i < 16; i++) { e[i] = __expf(-score[i]); tot += e[i]; }
        float inv = 1.0f / tot;
        #pragma unroll
        for (int i = 0; i < 16; i++) w[i] = e[i] * inv;
    }
    __syncthreads();

    // Block-contiguous partition: CTA bid owns [start, end) of float4 indices.
    const int q = n4 / NBLOCKS;
    const int r = n4 - q * NBLOCKS;
    const int start = blockIdx.x * q + min((int)blockIdx.x, r);
    const int cnt   = q + (blockIdx.x < r ? 1 : 0);
    const int end   = start + cnt;

    float acc0 = 0.0f, acc1 = 0.0f, acc2 = 0.0f, acc3 = 0.0f;

    // 4-way unroll over consecutive 4KB segments: each CTA streams its slice
    // sequentially (max row-buffer locality), 8 independent LDG.128 per iter.
    int i = start + threadIdx.x;
    for (; i + 3 * NTHREADS < end; i += 4 * NTHREADS) {
        float4 p0 = __ldcg(&pred[i]);
        float4 p1 = __ldcg(&pred[i + NTHREADS]);
        float4 p2 = __ldcg(&pred[i + 2 * NTHREADS]);
        float4 p3 = __ldcg(&pred[i + 3 * NTHREADS]);
        float4 t0 = __ldcg(&tru[i]);
        float4 t1 = __ldcg(&tru[i + NTHREADS]);
        float4 t2 = __ldcg(&tru[i + 2 * NTHREADS]);
        float4 t3 = __ldcg(&tru[i + 3 * NTHREADS]);
        acc0 += quad_term(w, p0, t0);
        acc1 += quad_term(w, p1, t1);
        acc2 += quad_term(w, p2, t2);
        acc3 += quad_term(w, p3, t3);
    }
    for (; i < end; i += NTHREADS) {
        acc0 += quad_term(w, __ldcg(&pred[i]), __ldcg(&tru[i]));
    }

    // Deterministic warp tree + fixed-order cross-warp sum.
    float v = (acc0 + acc1) + (acc2 + acc3);
    #pragma unroll
    for (int off = 16; off > 0; off >>= 1)
        v += __shfl_xor_sync(0xFFFFFFFFu, v, off);

    const int lane = threadIdx.x & 31;
    const int warp = threadIdx.x >> 5;
    if (lane == 0) swarp[warp] = v;
    __syncthreads();

    if (threadIdx.x == 0) {
        float bs = 0.0f;
        #pragma unroll
        for (int k = 0; k < NWARPS; k++) bs += swarp[k];
        g_partials[blockIdx.x] = bs;
        __threadfence();
        unsigned int prev = atomicAdd(&g_count, 1u);
        s_is_last = (prev == (unsigned int)(gridDim.x - 1));
    }
    __syncthreads();

    if (s_is_last) {
        // Fixed-order final reduction over 888 per-CTA partials.
        float a = 0.0f;
        for (int k = threadIdx.x; k < NBLOCKS; k += NTHREADS)
            a += g_partials[k];
        #pragma unroll
        for (int off = 16; off > 0; off >>= 1)
            a += __shfl_xor_sync(0xFFFFFFFFu, a, off);
        if (lane == 0) swarp[warp] = a;
        __syncthreads();
        if (threadIdx.x == 0) {
            float tot = 0.0f;
            #pragma unroll
            for (int k = 0; k < NWARPS; k++) tot += swarp[k];
            out[0] = tot * inv_B;
            g_count = 0;  // reset for next graph replay
        }
    }
}

extern "C" void kernel_launch(void* const* d_in, const int* in_sizes, int n_in,
                              void* d_out, int out_size)
{
    const float4* pred  = (const float4*)d_in[0];
    const float4* tru   = (const float4*)d_in[1];
    const float*  score = (const float*)d_in[2];
    float* out = (float*)d_out;

    long n  = (long)in_sizes[0];   // B * T
    int  n4 = (int)(n / 4);
    long B  = n / 48;              // T = 48

    gmgs_fused_kernel<<<NBLOCKS, NTHREADS>>>(pred, tru, score, n4,
                                             (float)(1.0 / (double)B), out);
}

// round 13
// speedup vs baseline: 1.0437x; 1.0437x over previous
#include <cuda_runtime.h>
#include <cuda_bf16.h>

// FINAL (R4 config, session-best 37.248us harness):
// one wave = 148 SMs x 6 CTAs (regs=40 @ 256 thr), static grid-stride
// partition, 4-way unroll (8 independent LDG.128/iter), fused deterministic
// last-block finish. At the measured dual-stream DRAM read ceiling
// (~5.6-5.8 TB/s, ~70% of 8 TB/s spec) — verified roofline across 10
// structurally distinct designs.
#define NBLOCKS 888
#define NTHREADS 256
#define NWARPS (NTHREADS / 32)

__device__ float g_partials[NBLOCKS];
__device__ unsigned int g_count = 0;

// class(x) = clamp(floor(x), -1, 2) + 1  in {0,1,2,3}
__device__ __forceinline__ int cls_of(float x) {
    int i = __float2int_rd(x);   // CVT.RMI
    i = max(i, -1);
    i = min(i, 2);
    return i + 1;
}

__device__ __forceinline__ float quad_term(const float* __restrict__ w,
                                           float4 p, float4 t) {
    float d0 = p.x - t.x;
    float d1 = p.y - t.y;
    float d2 = p.z - t.z;
    float d3 = p.w - t.w;

    float w0 = w[cls_of(t.x) * 4 + cls_of(p.x)];
    float w1 = w[cls_of(t.y) * 4 + cls_of(p.y)];
    float w2 = w[cls_of(t.z) * 4 + cls_of(p.z)];
    float w3 = w[cls_of(t.w) * 4 + cls_of(p.w)];

    float s01 = fmaf(d0 * d0, w0, d1 * d1 * w1);
    float s23 = fmaf(d2 * d2, w2, d3 * d3 * w3);
    return s01 + s23;
}

__global__ void __launch_bounds__(NTHREADS, 6)
gmgs_fused_kernel(const float4* __restrict__ pred,
                  const float4* __restrict__ tru,
                  const float* __restrict__ score,
                  int n4, float inv_B, float* __restrict__ out)
{
    __shared__ float w[16];
    __shared__ float swarp[NWARPS];
    __shared__ bool s_is_last;

    if (threadIdx.x == 0) {
        float e[16];
        float tot = 0.0f;
        #pragma unroll
        for (int i = 0; i < 16; i++) { e[i] = __expf(-score[i]); tot += e[i]; }
        float inv = 1.0f / tot;
        #pragma unroll
        for (int i = 0; i < 16; i++) w[i] = e[i] * inv;
    }
    __syncthreads();

    const int stride = NBLOCKS * NTHREADS;
    float acc0 = 0.0f, acc1 = 0.0f, acc2 = 0.0f, acc3 = 0.0f;

    int i = blockIdx.x * NTHREADS + threadIdx.x;
    // 4-way unrolled persistent grid-stride: 8 independent LDG.128 per iter.
    for (; i + 3 * stride < n4; i += 4 * stride) {
        float4 p0 = pred[i];
        float4 p1 = pred[i + stride];
        float4 p2 = pred[i + 2 * stride];
        float4 p3 = pred[i + 3 * stride];
        float4 t0 = tru[i];
        float4 t1 = tru[i + stride];
        float4 t2 = tru[i + 2 * stride];
        float4 t3 = tru[i + 3 * stride];
        acc0 += quad_term(w, p0, t0);
        acc1 += quad_term(w, p1, t1);
        acc2 += quad_term(w, p2, t2);
        acc3 += quad_term(w, p3, t3);
    }
    for (; i < n4; i += stride) {
        acc0 += quad_term(w, pred[i], tru[i]);
    }

    // Deterministic warp tree + fixed-order cross-warp sum.
    float v = (acc0 + acc1) + (acc2 + acc3);
    #pragma unroll
    for (int off = 16; off > 0; off >>= 1)
        v += __shfl_xor_sync(0xFFFFFFFFu, v, off);

    const int lane = threadIdx.x & 31;
    const int warp = threadIdx.x >> 5;
    if (lane == 0) swarp[warp] = v;
    __syncthreads();

    if (threadIdx.x == 0) {
        float bs = 0.0f;
        #pragma unroll
        for (int k = 0; k < NWARPS; k++) bs += swarp[k];
        g_partials[blockIdx.x] = bs;
        __threadfence();
        unsigned int prev = atomicAdd(&g_count, 1u);
        s_is_last = (prev == (unsigned int)(gridDim.x - 1));
    }
    __syncthreads();

    if (s_is_last) {
        // Fixed-order final reduction over 888 per-CTA partials.
        float a = 0.0f;
        for (int k = threadIdx.x; k < NBLOCKS; k += NTHREADS)
            a += g_partials[k];
        #pragma unroll
        for (int off = 16; off > 0; off >>= 1)
            a += __shfl_xor_sync(0xFFFFFFFFu, a, off);
        if (lane == 0) swarp[warp] = a;
        __syncthreads();
        if (threadIdx.x == 0) {
            float tot = 0.0f;
            #pragma unroll
            for (int k = 0; k < NWARPS; k++) tot += swarp[k];
            out[0] = tot * inv_B;
            g_count = 0;  // reset for next graph replay
        }
    }
}

extern "C" void kernel_launch(void* const* d_in, const int* in_sizes, int n_in,
                              void* d_out, int out_size)
{
    const float4* pred  = (const float4*)d_in[0];
    const float4* tru   = (const float4*)d_in[1];
    const float*  score = (const float*)d_in[2];
    float* out = (float*)d_out;

    long n  = (long)in_sizes[0];   // B * T
    int  n4 = (int)(n / 4);
    long B  = n / 48;              // T = 48

    gmgs_fused_kernel<<<NBLOCKS, NTHREADS>>>(pred, tru, score, n4,
                                             (float)(1.0 / (double)B), out);
}